// round 12
// baseline (speedup 1.0000x reference)
#include <cuda_runtime.h>
#include <cuda_fp16.h>
#include <cstdint>

// Problem constants
#define BATCH 16
#define NTOK  8192
#define FIN   256
#define FOUT  256
#define EPSBN 1e-5f
#define CTAS_PER_BATCH 64        // NTOK / BM

// Hybrid tiling: CTA 128x256. Rows 0..95 tensor (warp 48x64, 8 warps 2m x 4n),
// rows 96..127 via HFMA2 on the fma pipe (16 rows x 64 cols per warp).
#define BM 128
#define BN 256
#define BK 32
#define NCHUNK (FIN / BK)        // 8
#define THREADS 256
#define LDKH  40                 // fp16 row stride (halves)
#define B_STAGE_BYTES (BN * LDKH * 2)             // 20480
#define AH_BYTES      (BM * LDKH * 2)             // 10240
#define SMEM_ALLOC    (3 * B_STAGE_BYTES + 2 * AH_BYTES)  // 81920

// device-global scratch (no allocations allowed)
__device__ __half g_Wh  [FOUT * FIN];
__device__ float  g_sum  [BATCH * FOUT];
__device__ float  g_sumsq[BATCH * FOUT];
__device__ int    g_count[BATCH];

// ---------------------------------------------------------------------------
__device__ __forceinline__ uint32_t s2u(const void* p) {
    uint32_t a;
    asm("{ .reg .u64 t; cvta.to.shared.u64 t, %1; cvt.u32.u64 %0, t; }"
        : "=r"(a) : "l"(p));
    return a;
}
__device__ __forceinline__ void cp16(uint32_t saddr, const void* g) {
    asm volatile("cp.async.cg.shared.global [%0], [%1], 16;"
                 :: "r"(saddr), "l"(g));
}
__device__ __forceinline__ void mma_f16acc(uint32_t* c, const uint32_t* a,
                                           const uint32_t* b) {
    asm volatile(
        "mma.sync.aligned.m16n8k16.row.col.f16.f16.f16.f16 "
        "{%0,%1}, {%2,%3,%4,%5}, {%6,%7}, {%0,%1};"
        : "+r"(c[0]), "+r"(c[1])
        : "r"(a[0]), "r"(a[1]), "r"(a[2]), "r"(a[3]), "r"(b[0]), "r"(b[1]));
}
__device__ __forceinline__ void ldsm_x4(uint32_t* r, uint32_t saddr) {
    asm volatile("ldmatrix.sync.aligned.m8n8.x4.shared.b16 {%0,%1,%2,%3}, [%4];"
                 : "=r"(r[0]), "=r"(r[1]), "=r"(r[2]), "=r"(r[3]) : "r"(saddr));
}
__device__ __forceinline__ void ldsm_x2(uint32_t* r, uint32_t saddr) {
    asm volatile("ldmatrix.sync.aligned.m8n8.x2.shared.b16 {%0,%1}, [%2];"
                 : "=r"(r[0]), "=r"(r[1]) : "r"(saddr));
}
__device__ __forceinline__ __half2 u2h2(uint32_t u) {
    return *reinterpret_cast<__half2*>(&u);
}

// ---------------------------------------------------------------------------
// Kernel A: W fp32 -> fp16 + zero stats/counters (one launch)
// ---------------------------------------------------------------------------
__global__ void prep_kernel(const float* __restrict__ W) {
    int i = blockIdx.x * blockDim.x + threadIdx.x;      // 0 .. 32767
    if (i < FOUT * FIN / 2) {
        float2 f = reinterpret_cast<const float2*>(W)[i];
        reinterpret_cast<__half2*>(g_Wh)[i] = __floats2half2_rn(f.x, f.y);
    }
    if (i < BATCH * FOUT) { g_sum[i] = 0.0f; g_sumsq[i] = 0.0f; }
    if (i < BATCH) g_count[i] = 0;
}

// ---------------------------------------------------------------------------
// Kernel B: fused hybrid GEMM (tensor + HFMA2) + BatchNorm.
// grid = BATCH * 64 (batch = bx>>6 contiguous), block = 256
// ---------------------------------------------------------------------------
__global__ __launch_bounds__(THREADS, 1)
void gemm_bn_kernel(const float* __restrict__ x,
                    const float* __restrict__ bias,
                    const float* __restrict__ gamma,
                    const float* __restrict__ beta,
                    float* __restrict__ out)
{
    extern __shared__ char smem[];
    const uint32_t smem_u = s2u(smem);
    const uint32_t ah_u   = smem_u + 3 * B_STAGE_BYTES;

    const int tid  = threadIdx.x;
    const int lane = tid & 31;
    const int wid  = tid >> 5;

    const int bx = blockIdx.x;
    const int mt = bx & 63;
    const int b  = bx >> 6;
    const int m0 = mt * BM;

    const float* xb = x + ((size_t)b * NTOK + m0) * FIN;

    const int warp_m = wid >> 2;         // 0..1
    const int warp_n = wid & 3;          // 0..3

    // ---- tensor-region ldmatrix lane addressing (rows 0..95, 48/warp) ----
    const int j8  = lane >> 3;
    const int lr8 = lane & 7;
    const uint32_t a_lane_off =
        (uint32_t)(((warp_m * 48) + (j8 & 1) * 8 + lr8) * LDKH + (j8 >> 1) * 8) * 2u;
    const uint32_t b_lane_off =
        (uint32_t)(((warp_n * 64) + lr8) * LDKH + (j8 & 1) * 8) * 2u;

    // ---- fma-region lane mapping (rows 96..127; warp = 16 rows x 64 cols) ----
    const int rg   = lane >> 4;          // 0..1 row group of 8
    const int cg   = lane & 15;          // 0..15 col group of 4
    const int frow = 96 + warp_m * 16 + rg * 8;    // + rr (0..7)
    const int fcol = warp_n * 64 + cg * 4;         // + cc (0..3)

    // tensor accumulators: 2 chains x 3 mi x 8 ni
    uint32_t accL[3][8][2], accH[3][8][2];
#pragma unroll
    for (int mi = 0; mi < 3; mi++)
#pragma unroll
        for (int ni = 0; ni < 8; ni++) {
            accL[mi][ni][0] = 0u; accL[mi][ni][1] = 0u;
            accH[mi][ni][0] = 0u; accH[mi][ni][1] = 0u;
        }
    // fma accumulators: fp32, flushed per chunk
    float facc[8][4];
#pragma unroll
    for (int rr = 0; rr < 8; rr++)
#pragma unroll
        for (int cc = 0; cc < 4; cc++) facc[rr][cc] = 0.0f;

    // B stage loader (fp16 W): 256 rows x 4 granules = 1024 -> 4/thread
    auto load_B = [&](int c, int s) {
        const uint32_t bbase = smem_u + (uint32_t)(s * B_STAGE_BYTES);
        const int k0 = c * BK;
#pragma unroll
        for (int i = 0; i < 4; i++) {
            int idx = tid + i * THREADS;
            int r = idx >> 2, gi = idx & 3;
            cp16(bbase + (uint32_t)(r * LDKH + gi * 8) * 2u,
                 g_Wh + (size_t)r * FIN + k0 + gi * 8);
        }
    };

    // A chunk: 128 rows x 8 granules(16B) = 1024 -> 4/thread (LDG->cvt->STS)
    const int ar0 = tid >> 3;                 // 0..31
    const int agi = tid & 7;
    auto ldg_A = [&](int c, float4* v) {
        const int k0 = c * BK;
#pragma unroll
        for (int i = 0; i < 4; i++)
            v[i] = *(const float4*)(xb + (size_t)(ar0 + i * 32) * FIN + k0 + agi * 4);
    };
    auto sts_A = [&](const float4* v, int buf) {
        const uint32_t abase = ah_u + (uint32_t)(buf * AH_BYTES);
#pragma unroll
        for (int i = 0; i < 4; i++) {
            __half2 h0 = __floats2half2_rn(v[i].x, v[i].y);
            __half2 h1 = __floats2half2_rn(v[i].z, v[i].w);
            asm volatile("st.shared.v2.b32 [%0], {%1, %2};"
                :: "r"(abase + (uint32_t)((ar0 + i * 32) * LDKH + agi * 4) * 2u),
                   "r"(*(const uint32_t*)&h0), "r"(*(const uint32_t*)&h1));
        }
    };

    // prologue
    load_B(0, 0);
    asm volatile("cp.async.commit_group;" ::: "memory");
    load_B(1, 1);
    asm volatile("cp.async.commit_group;" ::: "memory");
    {
        float4 v[4];
        ldg_A(0, v);
        sts_A(v, 0);
    }

    for (int c = 0; c < NCHUNK; c++) {
        if (c + 1 < NCHUNK)
            asm volatile("cp.async.wait_group 1;" ::: "memory");
        else
            asm volatile("cp.async.wait_group 0;" ::: "memory");
        __syncthreads();   // B stage c arrived; A buf (c&1) stored

        float4 v[4];
        if (c + 1 < NCHUNK) ldg_A(c + 1, v);

        uint32_t (*acc)[8][2] = (c < 4) ? accL : accH;
        const uint32_t abase = ah_u + (uint32_t)((c & 1) * AH_BYTES) + a_lane_off;
        const uint32_t bbase = smem_u + (uint32_t)((c % 3) * B_STAGE_BYTES) + b_lane_off;

        // ---- tensor phase: rows 0..95 ----
#pragma unroll
        for (int ks = 0; ks < 2; ks++) {
            const uint32_t koff = (uint32_t)(ks * 16) * 2u;
            uint32_t af[3][4];
#pragma unroll
            for (int mi = 0; mi < 3; mi++)
                ldsm_x4(af[mi], abase + (uint32_t)(mi * 16 * LDKH) * 2u + koff);
            uint32_t bf[8][2];
#pragma unroll
            for (int ni = 0; ni < 8; ni++)
                ldsm_x2(bf[ni], bbase + (uint32_t)(ni * 8 * LDKH) * 2u + koff);
#pragma unroll
            for (int mi = 0; mi < 3; mi++)
#pragma unroll
                for (int ni = 0; ni < 8; ni++)
                    mma_f16acc(acc[mi][ni], af[mi], bf[ni]);
        }

        // ---- fma phase: rows 96..127 via HFMA2, k-paired, per-chunk flush ----
        {
            const __half* Afp = (const __half*)(smem + 3 * B_STAGE_BYTES
                                 + (c & 1) * AH_BYTES) + frow * LDKH;
            const __half* Bfp = (const __half*)(smem + (c % 3) * B_STAGE_BYTES)
                                 + fcol * LDKH;
#pragma unroll
            for (int grp = 0; grp < 2; grp++) {
                __half2 c2[4][4];
#pragma unroll
                for (int rr = 0; rr < 4; rr++)
#pragma unroll
                    for (int cc = 0; cc < 4; cc++)
                        c2[rr][cc] = __half2(__float2half_rn(0.f), __float2half_rn(0.f));
#pragma unroll
                for (int j2 = 0; j2 < 8; j2++) {    // 2 k-pairs per iter
                    uint2 a4[4], b4[4];
#pragma unroll
                    for (int rr = 0; rr < 4; rr++)
                        a4[rr] = *(const uint2*)(Afp + (grp * 4 + rr) * LDKH + 4 * j2);
#pragma unroll
                    for (int cc = 0; cc < 4; cc++)
                        b4[cc] = *(const uint2*)(Bfp + cc * LDKH + 4 * j2);
#pragma unroll
                    for (int rr = 0; rr < 4; rr++)
#pragma unroll
                        for (int cc = 0; cc < 4; cc++) {
                            c2[rr][cc] = __hfma2(u2h2(a4[rr].x), u2h2(b4[cc].x), c2[rr][cc]);
                            c2[rr][cc] = __hfma2(u2h2(a4[rr].y), u2h2(b4[cc].y), c2[rr][cc]);
                        }
                }
#pragma unroll
                for (int rr = 0; rr < 4; rr++)
#pragma unroll
                    for (int cc = 0; cc < 4; cc++) {
                        float2 f = __half22float2(c2[rr][cc]);
                        facc[grp * 4 + rr][cc] += f.x + f.y;
                    }
            }
        }

        if (c + 1 < NCHUNK) sts_A(v, (c + 1) & 1);
        if (c + 2 < NCHUNK) {
            load_B(c + 2, (c + 2) % 3);
            asm volatile("cp.async.commit_group;" ::: "memory");
        }
    }

    // ---------------- stats: column sums/sumsq -> global atomics -------------
    const int g2 = lane >> 2;
    const int t  = lane & 3;
    float* gs = &g_sum  [b * FOUT];
    float* gq = &g_sumsq[b * FOUT];

    // tensor region (48 rows per warp)
#pragma unroll
    for (int ni = 0; ni < 8; ni++) {
        const int cc = warp_n * 64 + ni * 8 + 2 * t;
        const float b0v = __ldg(&bias[cc]);
        const float b1v = __ldg(&bias[cc + 1]);
        float s0 = 0.f, s1 = 0.f, q0 = 0.f, q1 = 0.f;
#pragma unroll
        for (int mi = 0; mi < 3; mi++) {
            float2 l0 = __half22float2(*(__half2*)&accL[mi][ni][0]);
            float2 l1 = __half22float2(*(__half2*)&accL[mi][ni][1]);
            float2 h0 = __half22float2(*(__half2*)&accH[mi][ni][0]);
            float2 h1 = __half22float2(*(__half2*)&accH[mi][ni][1]);
            float v0 = l0.x + h0.x + b0v;
            float v1 = l0.y + h0.y + b1v;
            float v2 = l1.x + h1.x + b0v;
            float v3 = l1.y + h1.y + b1v;
            s0 += v0 + v2;  s1 += v1 + v3;
            q0 += v0 * v0 + v2 * v2;
            q1 += v1 * v1 + v3 * v3;
        }
#pragma unroll
        for (int m = 4; m <= 16; m <<= 1) {
            s0 += __shfl_xor_sync(0xFFFFFFFF, s0, m);
            s1 += __shfl_xor_sync(0xFFFFFFFF, s1, m);
            q0 += __shfl_xor_sync(0xFFFFFFFF, q0, m);
            q1 += __shfl_xor_sync(0xFFFFFFFF, q1, m);
        }
        if (lane < 4) {
            atomicAdd(&gs[cc], s0);  atomicAdd(&gs[cc + 1], s1);
            atomicAdd(&gq[cc], q0);  atomicAdd(&gq[cc + 1], q1);
        }
    }
    // fma region (16 rows per warp)
#pragma unroll
    for (int cc = 0; cc < 4; cc++) {
        const int cidx = fcol + cc;
        const float bv = __ldg(&bias[cidx]);
        float s = 0.f, q = 0.f;
#pragma unroll
        for (int rr = 0; rr < 8; rr++) {
            float v = facc[rr][cc] + bv;
            s += v;  q += v * v;
        }
        s += __shfl_xor_sync(0xFFFFFFFF, s, 16);
        q += __shfl_xor_sync(0xFFFFFFFF, q, 16);
        if (rg == 0) {
            atomicAdd(&gs[cidx], s);
            atomicAdd(&gq[cidx], q);
        }
    }

    // ---------------- per-batch spin barrier ---------------------------------
    __threadfence();
    __syncthreads();
    if (tid == 0) {
        atomicAdd(&g_count[b], 1);
        while (atomicAdd(&g_count[b], 0) < CTAS_PER_BATCH)
            __nanosleep(100);
    }
    __syncthreads();
    __threadfence();

    // ---------------- normalize from registers, write final output -----------
    const float invN = 1.0f / (float)NTOK;
    float* obase = out + ((size_t)b * NTOK + m0) * FOUT;

    // tensor region
#pragma unroll
    for (int ni = 0; ni < 8; ni++) {
        const int cc = warp_n * 64 + ni * 8 + 2 * t;
        const float b0v = __ldg(&bias[cc]);
        const float b1v = __ldg(&bias[cc + 1]);
        float mean0 = __ldcg(&gs[cc])     * invN;
        float mean1 = __ldcg(&gs[cc + 1]) * invN;
        float var0  = fmaxf(__ldcg(&gq[cc])     * invN - mean0 * mean0, 0.0f);
        float var1  = fmaxf(__ldcg(&gq[cc + 1]) * invN - mean1 * mean1, 0.0f);
        float sc0 = __ldg(&gamma[cc])     * rsqrtf(var0 + EPSBN);
        float sc1 = __ldg(&gamma[cc + 1]) * rsqrtf(var1 + EPSBN);
        float sh0 = __ldg(&beta[cc])     - mean0 * sc0;
        float sh1 = __ldg(&beta[cc + 1]) - mean1 * sc1;
#pragma unroll
        for (int mi = 0; mi < 3; mi++) {
            int r = warp_m * 48 + mi * 16 + g2;
            float2 l0 = __half22float2(*(__half2*)&accL[mi][ni][0]);
            float2 l1 = __half22float2(*(__half2*)&accL[mi][ni][1]);
            float2 h0 = __half22float2(*(__half2*)&accH[mi][ni][0]);
            float2 h1 = __half22float2(*(__half2*)&accH[mi][ni][1]);
            float v0 = (l0.x + h0.x + b0v) * sc0 + sh0;
            float v1 = (l0.y + h0.y + b1v) * sc1 + sh1;
            float v2 = (l1.x + h1.x + b0v) * sc0 + sh0;
            float v3 = (l1.y + h1.y + b1v) * sc1 + sh1;
            *(float2*)(obase + (size_t)r * FOUT + cc)       = make_float2(v0, v1);
            *(float2*)(obase + (size_t)(r + 8) * FOUT + cc) = make_float2(v2, v3);
        }
    }
    // fma region
    {
        float sc[4], sh[4], bv[4];
#pragma unroll
        for (int cc = 0; cc < 4; cc++) {
            const int cidx = fcol + cc;
            bv[cc] = __ldg(&bias[cidx]);
            float mean = __ldcg(&gs[cidx]) * invN;
            float var  = fmaxf(__ldcg(&gq[cidx]) * invN - mean * mean, 0.0f);
            sc[cc] = __ldg(&gamma[cidx]) * rsqrtf(var + EPSBN);
            sh[cc] = __ldg(&beta[cidx]) - mean * sc[cc];
        }
#pragma unroll
        for (int rr = 0; rr < 8; rr++) {
            float4 o;
            o.x = (facc[rr][0] + bv[0]) * sc[0] + sh[0];
            o.y = (facc[rr][1] + bv[1]) * sc[1] + sh[1];
            o.z = (facc[rr][2] + bv[2]) * sc[2] + sh[2];
            o.w = (facc[rr][3] + bv[3]) * sc[3] + sh[3];
            *(float4*)(obase + (size_t)(frow + rr) * FOUT + fcol) = o;
        }
    }
}

// ---------------------------------------------------------------------------
extern "C" void kernel_launch(void* const* d_in, const int* in_sizes, int n_in,
                              void* d_out, int out_size)
{
    const float* x     = (const float*)d_in[0];
    const float* W     = (const float*)d_in[1];
    const float* bias  = (const float*)d_in[2];
    const float* gamma = (const float*)d_in[3];
    const float* beta  = (const float*)d_in[4];
    float* out = (float*)d_out;

    cudaFuncSetAttribute(gemm_bn_kernel,
                         cudaFuncAttributeMaxDynamicSharedMemorySize,
                         SMEM_ALLOC);

    prep_kernel<<<FOUT * FIN / 2 / 256, 256>>>(W);
    gemm_bn_kernel<<<BATCH * CTAS_PER_BATCH, THREADS, SMEM_ALLOC>>>(
        x, bias, gamma, beta, out);
}

// round 14
// speedup vs baseline: 2.0517x; 2.0517x over previous
#include <cuda_runtime.h>
#include <cuda_fp16.h>
#include <cstdint>

// Problem constants
#define BATCH 16
#define NTOK  8192
#define FIN   256
#define FOUT  256
#define EPSBN 1e-5f
#define CTAS_PER_BATCH 64        // NTOK / BM

// GEMM tiling: CTA 128x256, warp 64x64, 8 warps (2m x 4n), fp16 MMA fp16 acc
#define BM 128
#define BN 256
#define BK 32
#define NCHUNK (FIN / BK)        // 8
#define THREADS 256
#define LDA32 36                 // fp32 A stage row stride (floats)
#define LDKH  40                 // fp16 row stride (halves)
#define A_STAGE_BYTES (BM * LDA32 * 4)            // 18432
#define B_STAGE_BYTES (BN * LDKH * 2)             // 20480
#define STAGE_BYTES   (A_STAGE_BYTES + B_STAGE_BYTES)   // 38912
#define NSTAGE 4
#define AH_BYTES      (BM * LDKH * 2)             // 10240
#define SMEM_ALLOC    (NSTAGE * STAGE_BYTES + 2 * AH_BYTES)  // 176128

// device-global scratch (no allocations allowed)
__device__ __half g_Wh  [FOUT * FIN];
__device__ float  g_sum  [BATCH * FOUT];
__device__ float  g_sumsq[BATCH * FOUT];
__device__ int    g_count[BATCH];

// ---------------------------------------------------------------------------
__device__ __forceinline__ uint32_t s2u(const void* p) {
    uint32_t a;
    asm("{ .reg .u64 t; cvta.to.shared.u64 t, %1; cvt.u32.u64 %0, t; }"
        : "=r"(a) : "l"(p));
    return a;
}
__device__ __forceinline__ void cp16(uint32_t saddr, const void* g) {
    asm volatile("cp.async.cg.shared.global [%0], [%1], 16;"
                 :: "r"(saddr), "l"(g));
}
__device__ __forceinline__ void mma_f16acc(uint32_t* c, const uint32_t* a,
                                           const uint32_t* b) {
    asm volatile(
        "mma.sync.aligned.m16n8k16.row.col.f16.f16.f16.f16 "
        "{%0,%1}, {%2,%3,%4,%5}, {%6,%7}, {%0,%1};"
        : "+r"(c[0]), "+r"(c[1])
        : "r"(a[0]), "r"(a[1]), "r"(a[2]), "r"(a[3]), "r"(b[0]), "r"(b[1]));
}
__device__ __forceinline__ void ldsm_x4(uint32_t* r, uint32_t saddr) {
    asm volatile("ldmatrix.sync.aligned.m8n8.x4.shared.b16 {%0,%1,%2,%3}, [%4];"
                 : "=r"(r[0]), "=r"(r[1]), "=r"(r[2]), "=r"(r[3]) : "r"(saddr));
}
__device__ __forceinline__ void ldsm_x2(uint32_t* r, uint32_t saddr) {
    asm volatile("ldmatrix.sync.aligned.m8n8.x2.shared.b16 {%0,%1}, [%2];"
                 : "=r"(r[0]), "=r"(r[1]) : "r"(saddr));
}

// ---------------------------------------------------------------------------
// Kernel A: W fp32 -> fp16 + zero stats/counters (one launch)
// ---------------------------------------------------------------------------
__global__ void prep_kernel(const float* __restrict__ W) {
    int i = blockIdx.x * blockDim.x + threadIdx.x;      // 0 .. 32767
    if (i < FOUT * FIN / 2) {
        float2 f = reinterpret_cast<const float2*>(W)[i];
        reinterpret_cast<__half2*>(g_Wh)[i] = __floats2half2_rn(f.x, f.y);
    }
    if (i < BATCH * FOUT) { g_sum[i] = 0.0f; g_sumsq[i] = 0.0f; }
    if (i < BATCH) g_count[i] = 0;
}

// ---------------------------------------------------------------------------
// Kernel B: fused GEMM + BatchNorm, single-sync pipelined mainloop.
// grid = BATCH * 64 (batch = bx>>6 contiguous), block = 256
// ---------------------------------------------------------------------------
__global__ __launch_bounds__(THREADS, 1)
void gemm_bn_kernel(const float* __restrict__ x,
                    const float* __restrict__ bias,
                    const float* __restrict__ gamma,
                    const float* __restrict__ beta,
                    float* __restrict__ out)
{
    extern __shared__ char smem[];
    const uint32_t smem_u = s2u(smem);
    const uint32_t ah_u   = smem_u + NSTAGE * STAGE_BYTES;

    const int tid  = threadIdx.x;
    const int lane = tid & 31;
    const int wid  = tid >> 5;

    const int bx = blockIdx.x;
    const int mt = bx & 63;
    const int b  = bx >> 6;
    const int m0 = mt * BM;

    const float* xb = x + ((size_t)b * NTOK + m0) * FIN;

    const int warp_m = wid >> 2;         // 0..1 -> 64-row slice
    const int warp_n = wid & 3;          // 0..3 -> 64-col slice

    // ldmatrix lane address components (mapping verified in R10)
    const int j8  = lane >> 3;           // 0..3
    const int lr8 = lane & 7;            // 0..7
    const uint32_t a_lane_off =
        (uint32_t)(((warp_m * 64) + (j8 & 1) * 8 + lr8) * LDKH + (j8 >> 1) * 8) * 2u;
    const uint32_t b_lane_off =
        (uint32_t)(((warp_n * 64) + lr8) * LDKH + (j8 & 1) * 8) * 2u;

    // two independent fp16 accumulator chains (chunks 0-3 / 4-7)
    uint32_t accL[4][8][2], accH[4][8][2];
#pragma unroll
    for (int mi = 0; mi < 4; mi++)
#pragma unroll
        for (int ni = 0; ni < 8; ni++) {
            accL[mi][ni][0] = 0u; accL[mi][ni][1] = 0u;
            accH[mi][ni][0] = 0u; accH[mi][ni][1] = 0u;
        }

    // stage loader: A fp32 (1024 x 16B) + B fp16 (1024 x 16B)
    auto load_stage = [&](int c, int s) {
        const uint32_t abase = smem_u + (uint32_t)(s * STAGE_BYTES);
        const uint32_t bbase = abase + A_STAGE_BYTES;
        const int k0 = c * BK;
#pragma unroll
        for (int i = 0; i < 4; i++) {        // A: 128 rows x 8 granules
            int idx = tid + i * THREADS;
            int r = idx >> 3, gi = idx & 7;
            cp16(abase + (uint32_t)(r * LDA32 + gi * 4) * 4u,
                 xb + (size_t)r * FIN + k0 + gi * 4);
        }
#pragma unroll
        for (int i = 0; i < 4; i++) {        // B: 256 rows x 4 granules (fp16)
            int idx = tid + i * THREADS;
            int r = idx >> 2, gi = idx & 3;
            cp16(bbase + (uint32_t)(r * LDKH + gi * 8) * 2u,
                 g_Wh + (size_t)r * FIN + k0 + gi * 8);
        }
    };

    // convert fp32 A of stage c -> fp16 Ah buffer (same granules this thread
    // loaded via cp.async -> self-visibility after wait_group suffices)
    auto convert_A = [&](int c, int buf) {
        const float* Sa = (const float*)(smem + (c & (NSTAGE - 1)) * STAGE_BYTES);
        const uint32_t abase = ah_u + (uint32_t)(buf * AH_BYTES);
#pragma unroll
        for (int i = 0; i < 4; i++) {
            int idx = tid + i * THREADS;
            int r = idx >> 3, c4 = idx & 7;
            float4 v = *(const float4*)(Sa + r * LDA32 + c4 * 4);
            __half2 h0 = __floats2half2_rn(v.x, v.y);
            __half2 h1 = __floats2half2_rn(v.z, v.w);
            asm volatile("st.shared.v2.b32 [%0], {%1, %2};"
                :: "r"(abase + (uint32_t)(r * LDKH + c4 * 4) * 2u),
                   "r"(*(const uint32_t*)&h0), "r"(*(const uint32_t*)&h1));
        }
    };

    // prologue: stages 0,1,2 in flight; stage 0 converted into Ah[0]
    load_stage(0, 0);
    asm volatile("cp.async.commit_group;" ::: "memory");
    load_stage(1, 1);
    asm volatile("cp.async.commit_group;" ::: "memory");
    load_stage(2, 2);
    asm volatile("cp.async.commit_group;" ::: "memory");
    asm volatile("cp.async.wait_group 2;" ::: "memory");   // stage 0 complete
    convert_A(0, 0);

    // Invariants at top of iter c:
    //   stages <= c complete and (after sync) visible to all threads
    //   Ah[c&1] converted (iter c-1 or prologue)
    for (int c = 0; c < NCHUNK; c++) {
        __syncthreads();   // publishes Ah[c&1] + B stage c; frees buf (c-1)&3

        if (c + 3 < NCHUNK) {          // buffer (c+3)&3 == (c-1)&3: free now
            load_stage(c + 3, (c + 3) & (NSTAGE - 1));
            asm volatile("cp.async.commit_group;" ::: "memory");
        }

        uint32_t (*acc)[8][2] = (c < 4) ? accL : accH;
        const uint32_t abase = ah_u + (uint32_t)((c & 1) * AH_BYTES) + a_lane_off;
        const uint32_t bbase = smem_u + (uint32_t)((c & (NSTAGE - 1)) * STAGE_BYTES)
                               + A_STAGE_BYTES + b_lane_off;

        // ---- MMA phase ----
#pragma unroll
        for (int ks = 0; ks < 2; ks++) {
            const uint32_t koff = (uint32_t)(ks * 16) * 2u;
            uint32_t af[4][4];
#pragma unroll
            for (int mi = 0; mi < 4; mi++)
                ldsm_x4(af[mi], abase + (uint32_t)(mi * 16 * LDKH) * 2u + koff);
            uint32_t bf[8][2];
#pragma unroll
            for (int ni = 0; ni < 8; ni++)
                ldsm_x2(bf[ni], bbase + (uint32_t)(ni * 8 * LDKH) * 2u + koff);
#pragma unroll
            for (int mi = 0; mi < 4; mi++)
#pragma unroll
                for (int ni = 0; ni < 8; ni++)
                    mma_f16acc(acc[mi][ni], af[mi], bf[ni]);
        }

        // ---- ensure stage c+1 arrived, then convert it into Ah[(c+1)&1] ----
        // pending groups before wait: subset of {c+1, c+2, c+3} (c<=4),
        // {6,7} at c=5, {7} at c=6.
        if (c + 1 < NCHUNK) {
            if (c <= 4)
                asm volatile("cp.async.wait_group 2;" ::: "memory");
            else if (c == 5)
                asm volatile("cp.async.wait_group 1;" ::: "memory");
            else
                asm volatile("cp.async.wait_group 0;" ::: "memory");
            convert_A(c + 1, (c + 1) & 1);
        }
    }

    // ---------------- stats: column sums/sumsq -> global atomics -------------
    const int g2 = lane >> 2;           // 0..7
    const int t  = lane & 3;            // 0..3
    float* gs = &g_sum  [b * FOUT];
    float* gq = &g_sumsq[b * FOUT];
#pragma unroll
    for (int ni = 0; ni < 8; ni++) {
        const int cc = warp_n * 64 + ni * 8 + 2 * t;
        const float b0v = __ldg(&bias[cc]);
        const float b1v = __ldg(&bias[cc + 1]);
        float s0 = 0.f, s1 = 0.f, q0 = 0.f, q1 = 0.f;
#pragma unroll
        for (int mi = 0; mi < 4; mi++) {
            float2 l0 = __half22float2(*(__half2*)&accL[mi][ni][0]);
            float2 l1 = __half22float2(*(__half2*)&accL[mi][ni][1]);
            float2 h0 = __half22float2(*(__half2*)&accH[mi][ni][0]);
            float2 h1 = __half22float2(*(__half2*)&accH[mi][ni][1]);
            float v0 = l0.x + h0.x + b0v;
            float v1 = l0.y + h0.y + b1v;
            float v2 = l1.x + h1.x + b0v;
            float v3 = l1.y + h1.y + b1v;
            s0 += v0 + v2;  s1 += v1 + v3;
            q0 += v0 * v0 + v2 * v2;
            q1 += v1 * v1 + v3 * v3;
        }
#pragma unroll
        for (int m = 4; m <= 16; m <<= 1) {
            s0 += __shfl_xor_sync(0xFFFFFFFF, s0, m);
            s1 += __shfl_xor_sync(0xFFFFFFFF, s1, m);
            q0 += __shfl_xor_sync(0xFFFFFFFF, q0, m);
            q1 += __shfl_xor_sync(0xFFFFFFFF, q1, m);
        }
        if (lane < 4) {
            atomicAdd(&gs[cc], s0);  atomicAdd(&gs[cc + 1], s1);
            atomicAdd(&gq[cc], q0);  atomicAdd(&gq[cc + 1], q1);
        }
    }

    // ---------------- per-batch spin barrier ---------------------------------
    __threadfence();
    __syncthreads();
    if (tid == 0) {
        atomicAdd(&g_count[b], 1);
        while (atomicAdd(&g_count[b], 0) < CTAS_PER_BATCH)
            __nanosleep(100);
    }
    __syncthreads();
    __threadfence();

    // ---------------- normalize from registers, write final output -----------
    const float invN = 1.0f / (float)NTOK;
    float* obase = out + ((size_t)b * NTOK + m0) * FOUT;

#pragma unroll
    for (int ni = 0; ni < 8; ni++) {
        const int cc = warp_n * 64 + ni * 8 + 2 * t;
        const float b0v = __ldg(&bias[cc]);
        const float b1v = __ldg(&bias[cc + 1]);
        float mean0 = __ldcg(&gs[cc])     * invN;
        float mean1 = __ldcg(&gs[cc + 1]) * invN;
        float var0  = fmaxf(__ldcg(&gq[cc])     * invN - mean0 * mean0, 0.0f);
        float var1  = fmaxf(__ldcg(&gq[cc + 1]) * invN - mean1 * mean1, 0.0f);
        float sc0 = __ldg(&gamma[cc])     * rsqrtf(var0 + EPSBN);
        float sc1 = __ldg(&gamma[cc + 1]) * rsqrtf(var1 + EPSBN);
        float sh0 = __ldg(&beta[cc])     - mean0 * sc0;
        float sh1 = __ldg(&beta[cc + 1]) - mean1 * sc1;
#pragma unroll
        for (int mi = 0; mi < 4; mi++) {
            int r = warp_m * 64 + mi * 16 + g2;
            float2 l0 = __half22float2(*(__half2*)&accL[mi][ni][0]);
            float2 l1 = __half22float2(*(__half2*)&accL[mi][ni][1]);
            float2 h0 = __half22float2(*(__half2*)&accH[mi][ni][0]);
            float2 h1 = __half22float2(*(__half2*)&accH[mi][ni][1]);
            float v0 = (l0.x + h0.x + b0v) * sc0 + sh0;
            float v1 = (l0.y + h0.y + b1v) * sc1 + sh1;
            float v2 = (l1.x + h1.x + b0v) * sc0 + sh0;
            float v3 = (l1.y + h1.y + b1v) * sc1 + sh1;
            *(float2*)(obase + (size_t)r * FOUT + cc)       = make_float2(v0, v1);
            *(float2*)(obase + (size_t)(r + 8) * FOUT + cc) = make_float2(v2, v3);
        }
    }
}

// ---------------------------------------------------------------------------
extern "C" void kernel_launch(void* const* d_in, const int* in_sizes, int n_in,
                              void* d_out, int out_size)
{
    const float* x     = (const float*)d_in[0];
    const float* W     = (const float*)d_in[1];
    const float* bias  = (const float*)d_in[2];
    const float* gamma = (const float*)d_in[3];
    const float* beta  = (const float*)d_in[4];
    float* out = (float*)d_out;

    cudaFuncSetAttribute(gemm_bn_kernel,
                         cudaFuncAttributeMaxDynamicSharedMemorySize,
                         SMEM_ALLOC);

    prep_kernel<<<FOUT * FIN / 2 / 256, 256>>>(W);
    gemm_bn_kernel<<<BATCH * CTAS_PER_BATCH, THREADS, SMEM_ALLOC>>>(
        x, bias, gamma, beta, out);
}